// round 8
// baseline (speedup 1.0000x reference)
#include <cuda_runtime.h>
#include <cuda_fp16.h>
#include <cstdint>

// GeometryOptimalTransport: sparse Sinkhorn attention. b=4, n=4096, d=64.
// R8 = R7 resubmitted (previous round failed on broker infra, kernel never ran).
//     Pass blocks = 1024 threads / 32 rows (staging traffic /4);
//     final = 8-cell superblocks, 128 blocks -> 1 CTA/SM, halo L1-resident.

#define BB 4
#define NN 4096
#define DD 64
#define STRIDE 640            // max valid neighbors ~515+6sigma; multiple of 128
#define WPB 8
#define THREADS 256
#define NSLAB 16
#define NXBIN 16
#define NCELL2 16             // 16x16 target cells for the epilogue
#define TCAP2 64              // targets per cell cap (mean 16)
#define SCELL 8               // cells per final superblock
#define SENTINEL 0xFC000000u  // off 0 | f16 -inf -> ex2() == 0

// log2(e) / (EPS + 1e-8), EPS = 0.01
__device__ __constant__ float C2 = (float)(1.4426950408889634 / 0.01000001);

__device__ uint32_t g_listT[BB * NN * STRIDE];   // entries: (f16 lk2)<<16 | idx<<2
__device__ uint32_t g_listS[BB * NN * STRIDE];
__device__ int g_cntT[BB * NN];                  // padded counts (multiple of 128)
__device__ int g_cntS[BB * NN];
__device__ float g_u2[BB * NN];                  // u * log2(e)
__device__ float g_v2[BB * NN];                  // v * log2(e)
__device__ __half2 g_Vh[BB * NN * (DD / 2)];     // V in half2 (2MB)
// stage 1: y-slab sorted; stage 2: (yslab,xbin) sorted
__device__ float2 g_sortloc[2][BB][NN];
__device__ unsigned short g_sortid[2][BB][NN];
__device__ int g_slabstart[2][BB][NSLAB + 1];
__device__ float2 g_loc2[2][BB][NN];
__device__ unsigned short g_id2[2][BB][NN];
__device__ int g_binstart[2][BB][NSLAB * NXBIN + 1];
// target cell lists for the epilogue
__device__ int g_tcnt[BB * NCELL2 * NCELL2];
__device__ int g_tlist[BB * NCELL2 * NCELL2][TCAP2];

static __device__ __forceinline__ float ex2f(float x) {
    float y; asm("ex2.approx.ftz.f32 %0, %1;" : "=f"(y) : "f"(x)); return y;
}
static __device__ __forceinline__ float lg2f(float x) {
    float y; asm("lg2.approx.f32 %0, %1;" : "=f"(y) : "f"(x)); return y;
}
// gather float at byte offset (entry low 16 bits hold idx*4)
static __device__ __forceinline__ float gat(const float* s, uint32_t e) {
    return *reinterpret_cast<const float*>(
        reinterpret_cast<const char*>(s) + (e & 0xFFFCu));
}
static __device__ __forceinline__ float lk2of(uint32_t e) {
    return __half2float(__ushort_as_half((unsigned short)(e >> 16)));
}

// ---------------------------------------------------------------------------
// Stage 1: deterministic y-slab counting sort (warp-per-slab, ballot
// compaction). Block (0,0) also zeroes g_tcnt.
// ---------------------------------------------------------------------------
__global__ void slab_sort(const float2* __restrict__ tlocs,
                          const float2* __restrict__ slocs)
{
    const int b = blockIdx.x, mode = blockIdx.y;
    const float2* cl = (mode ? tlocs : slocs) + (size_t)b * NN;
    __shared__ int s_cnt[NSLAB + 1];
    const int tid = threadIdx.x, wid = tid >> 5, lane = tid & 31;  // 16 warps

    if (blockIdx.x == 0 && blockIdx.y == 0)
        for (int k = tid; k < BB * NCELL2 * NCELL2; k += 512) g_tcnt[k] = 0;

    int c = 0;
    for (int i0 = 0; i0 < NN; i0 += 32) {
        const float2 p = cl[i0 + lane];
        const int sl = min(max((int)(p.y * (float)NSLAB), 0), NSLAB - 1);
        c += __popc(__ballot_sync(0xffffffffu, sl == wid));
    }
    if (lane == 0) s_cnt[wid + 1] = c;
    __syncthreads();
    if (tid == 0) {
        s_cnt[0] = 0;
        for (int k = 1; k <= NSLAB; k++) s_cnt[k] += s_cnt[k - 1];
    }
    __syncthreads();
    int base = s_cnt[wid];
    if (tid <= NSLAB) g_slabstart[mode][b][tid] = s_cnt[tid];
    for (int i0 = 0; i0 < NN; i0 += 32) {
        const float2 p = cl[i0 + lane];
        const int sl = min(max((int)(p.y * (float)NSLAB), 0), NSLAB - 1);
        const bool m = (sl == wid);
        const unsigned bal = __ballot_sync(0xffffffffu, m);
        if (m) {
            const int o = base + __popc(bal & ((1u << lane) - 1u));
            g_sortloc[mode][b][o] = p;
            g_sortid[mode][b][o] = (unsigned short)(i0 + lane);
        }
        base += __popc(bal);
    }
}

// ---------------------------------------------------------------------------
// Stage 2: within each y-slab, deterministic x-bin sort.
// ---------------------------------------------------------------------------
__global__ void xbin_sort()
{
    const int b = blockIdx.x, mode = blockIdx.y;
    const int tid = threadIdx.x, wid = tid >> 5, lane = tid & 31;  // 16 warps
    const int beg = g_slabstart[mode][b][wid];
    const int end = g_slabstart[mode][b][wid + 1];

    int base = beg;
    for (int xb = 0; xb < NXBIN; xb++) {
        if (lane == 0) g_binstart[mode][b][wid * NXBIN + xb] = base;
        for (int i0 = beg; i0 < end; i0 += 32) {
            const int i = i0 + lane;
            bool m = false;
            float2 p; unsigned short id = 0;
            if (i < end) {
                p = g_sortloc[mode][b][i];
                id = g_sortid[mode][b][i];
                const int xbin = min(max((int)(p.x * (float)NXBIN), 0), NXBIN - 1);
                m = (xbin == xb);
            }
            const unsigned bal = __ballot_sync(0xffffffffu, m);
            if (m) {
                const int o = base + __popc(bal & ((1u << lane) - 1u));
                g_loc2[mode][b][o] = p;
                g_id2[mode][b][o] = id;
            }
            base += __popc(bal);
        }
    }
    if (wid == NSLAB - 1 && lane == 0)
        g_binstart[mode][b][NSLAB * NXBIN] = end;
}

// ---------------------------------------------------------------------------
// Bin targets into 16x16 cells (atomic order irrelevant: per-target outputs
// are computed independently).
// ---------------------------------------------------------------------------
__global__ void bin_targets(const float2* __restrict__ tlocs)
{
    const int i = blockIdx.x * THREADS + threadIdx.x;
    if (i >= BB * NN) return;
    const int b = i >> 12, t = i & (NN - 1);
    const float2 p = tlocs[i];
    const int cx = min(max((int)(p.x * (float)NCELL2), 0), NCELL2 - 1);
    const int cy = min(max((int)(p.y * (float)NCELL2), 0), NCELL2 - 1);
    const int cell = b * NCELL2 * NCELL2 + cy * NCELL2 + cx;
    const int pos = atomicAdd(&g_tcnt[cell], 1);
    if (pos < TCAP2) g_tlist[cell][pos] = t;
}

// ---------------------------------------------------------------------------
// V (f32) -> half2 copy.
// ---------------------------------------------------------------------------
__global__ void convert_vh(const float2* __restrict__ feats2)
{
    const int i = blockIdx.x * THREADS + threadIdx.x;   // over BB*NN*32
    const float2 v = feats2[i];
    g_Vh[i] = __floats2half2_rn(v.x, v.y);
}

// ---------------------------------------------------------------------------
// Build compacted pair lists; candidates limited to the (yslab,xbin) window
// covering the 0.2 radius. Entries: (f16 lk2)<<16 | idx<<2. Pads to a
// multiple of 128 with SENTINEL. mode 1 also inits v2 = 0.
// ---------------------------------------------------------------------------
__global__ void build_lists(const float2* __restrict__ tlocs,
                            const float2* __restrict__ slocs)
{
    __shared__ float2 s_loc[NN];
    __shared__ unsigned short s_id[NN];
    __shared__ int s_bs[NSLAB * NXBIN + 1];       // 257 entries
    const int mode = blockIdx.z;
    const float2* row_locs = (mode ? slocs : tlocs);
    const int b = blockIdx.y;
    const int tid = threadIdx.x;
    #pragma unroll
    for (int k = 0; k < NN / THREADS; k++) {
        s_loc[tid + k * THREADS] = g_loc2[mode][b][tid + k * THREADS];
        s_id[tid + k * THREADS]  = g_id2[mode][b][tid + k * THREADS];
    }
    s_bs[tid] = g_binstart[mode][b][tid];
    if (tid == 0)
        s_bs[NSLAB * NXBIN] = g_binstart[mode][b][NSLAB * NXBIN];
    __syncthreads();

    const int wid = tid >> 5, lane = tid & 31;
    const int r = blockIdx.x * WPB + wid;
    const int g = b * NN + r;
    const float2 rl = row_locs[(size_t)b * NN + r];
    uint32_t* lp = (mode ? g_listS : g_listT) + (size_t)g * STRIDE;

    const int lo  = max((int)((rl.y - 0.2001f) * (float)NSLAB), 0);
    const int hi  = min((int)((rl.y + 0.2001f) * (float)NSLAB), NSLAB - 1);
    const int xlo = max((int)((rl.x - 0.2001f) * (float)NXBIN), 0);
    const int xhi = min((int)((rl.x + 0.2001f) * (float)NXBIN), NXBIN - 1);

    int n = 0;
    for (int s = lo; s <= hi; s++) {
        const int beg = s_bs[s * NXBIN + xlo];
        const int end = s_bs[s * NXBIN + xhi + 1];
        for (int i0 = beg; i0 < end; i0 += 32) {
            const int i = i0 + lane;
            bool pred = false;
            float dsq = 0.0f;
            unsigned short sid = 0;
            if (i < end) {
                const float2 c = s_loc[i];
                const float dx = rl.x - c.x;
                const float dy = rl.y - c.y;
                // match reference rounding: mul, mul, add (no fma contraction)
                dsq = __fadd_rn(__fmul_rn(dx, dx), __fmul_rn(dy, dy));
                pred = dsq < 0.04f;
                sid = s_id[i];
            }
            const unsigned bal = __ballot_sync(0xffffffffu, pred);
            if (pred) {
                const float lk2 = dsq * (-C2);
                const unsigned short h = __half_as_ushort(__float2half(lk2));
                const uint32_t e = ((uint32_t)sid << 2) | ((uint32_t)h << 16);
                const int ofs = n + __popc(bal & ((1u << lane) - 1u));
                if (ofs < STRIDE) lp[ofs] = e;
            }
            n += __popc(bal);
        }
    }
    n = min(n, STRIDE);
    const int npad = min((n + 127) & ~127, STRIDE);
    for (int i = n + lane; i < npad; i += 32) lp[i] = SENTINEL;
    if (lane == 0) {
        (mode ? g_cntS : g_cntT)[g] = npad;
        if (mode) g_v2[g] = 0.0f;
    }
}

// ---------------------------------------------------------------------------
// One Sinkhorn half-iteration (base-2 domain). 1024 threads, 32 rows/block
// (one per warp) -> dual-vector staging traffic amortized 4x vs 256-thread
// blocks. Row's <=5 list chunks loaded up-front (MLP 5).
// ---------------------------------------------------------------------------
static __device__ __forceinline__ float chunk_sum(uint4 q, const float* s_in) {
    float a;
    a  = ex2f(lk2of(q.x) + gat(s_in, q.x));
    a += ex2f(lk2of(q.y) + gat(s_in, q.y));
    a += ex2f(lk2of(q.z) + gat(s_in, q.z));
    a += ex2f(lk2of(q.w) + gat(s_in, q.w));
    return a;
}

__global__ void __launch_bounds__(1024) sinkhorn_pass(int dir)
{
    __shared__ float s_in[NN];
    const int b = blockIdx.y;
    const int tid = threadIdx.x;
    const float* vin = dir ? g_u2 : g_v2;
    reinterpret_cast<float4*>(s_in)[tid] =
        reinterpret_cast<const float4*>(vin + b * NN)[tid];   // 1024 x 16B
    __syncthreads();

    const int wid = tid >> 5, lane = tid & 31;
    const int g = b * NN + blockIdx.x * 32 + wid;
    const int n = (dir ? g_cntS : g_cntT)[g];      // multiple of 128, <= 640
    const uint4* lp = reinterpret_cast<const uint4*>(
        (dir ? g_listS : g_listT) + (size_t)g * STRIDE);
    const int nc = n >> 7;                         // chunk count, 0..5

    uint4 q0, q1, q2, q3, q4;
    if (nc > 0) q0 = lp[lane];
    if (nc > 1) q1 = lp[32 + lane];
    if (nc > 2) q2 = lp[64 + lane];
    if (nc > 3) q3 = lp[96 + lane];
    if (nc > 4) q4 = lp[128 + lane];

    float acc = 0.0f;
    if (nc > 0) acc += chunk_sum(q0, s_in);
    if (nc > 1) acc += chunk_sum(q1, s_in);
    if (nc > 2) acc += chunk_sum(q2, s_in);
    if (nc > 3) acc += chunk_sum(q3, s_in);
    if (nc > 4) acc += chunk_sum(q4, s_in);

    #pragma unroll
    for (int o = 16; o; o >>= 1) acc += __shfl_xor_sync(0xffffffffu, acc, o);
    if (lane == 0) (dir ? g_v2 : g_u2)[g] = -lg2f(acc);
}

// ---------------------------------------------------------------------------
// Epilogue: one 1024-thread CTA per (8-cell superblock, batch) -> 128 CTAs,
// one per SM, so the superblock's V halo (~218KB of half2 rows) stays
// L1-resident. Warps draw targets from the pooled 8-cell list (smem prefix)
// for load balance. Inner loop: smem (w, off) broadcast + half2 V FMAs.
// ---------------------------------------------------------------------------
__global__ void __launch_bounds__(1024) final_kernel(float* __restrict__ out)
{
    __shared__ float s_v[NN];                  // v2 for this batch (16KB)
    __shared__ float2 s_w[32][32];             // (w, off-as-float) per warp (8KB)
    __shared__ int s_pref[SCELL + 1];
    const int b = blockIdx.y;
    const int cell0 = blockIdx.x * SCELL;      // grid.x = 256/SCELL = 32
    const int tid = threadIdx.x, wid = tid >> 5, lane = tid & 31;  // 32 warps

    reinterpret_cast<float4*>(s_v)[tid] =
        reinterpret_cast<const float4*>(g_v2 + b * NN)[tid];
    if (tid == 0) {
        int acc = 0;
        s_pref[0] = 0;
        #pragma unroll
        for (int k = 0; k < SCELL; k++) {
            acc += min(g_tcnt[b * NCELL2 * NCELL2 + cell0 + k], TCAP2);
            s_pref[k + 1] = acc;
        }
    }
    __syncthreads();

    const int tot = s_pref[SCELL];
    const __half2* Vb = g_Vh + (size_t)b * NN * (DD / 2);

    for (int ti = wid; ti < tot; ti += 32) {
        int k = 0;
        #pragma unroll
        for (int kk = 1; kk < SCELL; kk++) k += (ti >= s_pref[kk]);
        const int t = g_tlist[b * NCELL2 * NCELL2 + cell0 + k][ti - s_pref[k]];
        const int g = b * NN + t;
        const int n = g_cntT[g];               // multiple of 128 (or 0)
        const uint32_t* lp = g_listT + (size_t)g * STRIDE;
        const float u2t = g_u2[g];

        float2 acc = make_float2(0.0f, 0.0f);
        uint32_t e = (n > 0) ? lp[lane] : SENTINEL;
        for (int i0 = 0; i0 < n; i0 += 32) {
            const float w = ex2f(lk2of(e) + u2t + gat(s_v, e));
            s_w[wid][lane] = make_float2(w, __uint_as_float(e & 0xFFFCu));
            __syncwarp();
            if (i0 + 32 < n) e = lp[i0 + 32 + lane];   // prefetch next chunk
            #pragma unroll 8
            for (int j = 0; j < 32; j++) {
                const float2 p = s_w[wid][j];
                if (p.x != 0.0f) {   // warp-uniform; skips padding/underflow
                    const float2 vv = __half22float2(
                        Vb[((size_t)__float_as_uint(p.y) << 3) + lane]);
                    acc.x = fmaf(p.x, vv.x, acc.x);
                    acc.y = fmaf(p.x, vv.y, acc.y);
                }
            }
            __syncwarp();
        }
        reinterpret_cast<float2*>(out)[(size_t)g * (DD / 2) + lane] = acc;
    }
}

// ---------------------------------------------------------------------------
extern "C" void kernel_launch(void* const* d_in, const int* in_sizes, int n_in,
                              void* d_out, int out_size)
{
    const float* feats  = (const float*)d_in[0];        // (b, src, 64) f32
    const float2* slocs = (const float2*)d_in[1];       // (b, src, 2)  f32
    const float2* tlocs = (const float2*)d_in[2];       // (b, tgt, 2)  f32
    float* out = (float*)d_out;                          // (b, tgt, 64) f32

    slab_sort<<<dim3(BB, 2), 512>>>(tlocs, slocs);
    xbin_sort<<<dim3(BB, 2), 512>>>();
    bin_targets<<<(BB * NN + THREADS - 1) / THREADS, THREADS>>>(tlocs);
    convert_vh<<<BB * NN * (DD / 2) / THREADS, THREADS>>>((const float2*)feats);
    build_lists<<<dim3(NN / WPB, BB, 2), THREADS>>>(tlocs, slocs);

    for (int it = 0; it < 8; it++) {
        sinkhorn_pass<<<dim3(NN / 32, BB), 1024>>>(0);  // u <- v
        sinkhorn_pass<<<dim3(NN / 32, BB), 1024>>>(1);  // v <- u
    }

    final_kernel<<<dim3(NCELL2 * NCELL2 / SCELL, BB), 1024>>>(out);
}

// round 10
// speedup vs baseline: 1.0734x; 1.0734x over previous
#include <cuda_runtime.h>
#include <cuda_fp16.h>
#include <cstdint>

// GeometryOptimalTransport: sparse Sinkhorn attention. b=4, n=4096, d=64.
// R10 = R9 resubmitted (broker infra failed twice; kernel never ran).
//       LINEAR-DOMAIN lists: entries store K = exp(-dsq/eps) as f16;
//       duals iterate as eu=2^u, ev=2^v. Inner loops are LDS+FMA only
//       (one MUFU rcp per row per pass; zero transcendentals per pair).

#define BB 4
#define NN 4096
#define DD 64
#define STRIDE 640            // max valid neighbors ~515+6sigma; multiple of 128
#define WPB 8
#define THREADS 256
#define NSLAB 16
#define NXBIN 16
#define NCELL2 16             // 16x16 target cells for the epilogue
#define TCAP2 64              // targets per cell cap (mean 16)
#define SENTINEL 0u           // K = 0, off = 0 -> contributes exactly 0

// log2(e) / (EPS + 1e-8), EPS = 0.01
__device__ __constant__ float C2 = (float)(1.4426950408889634 / 0.01000001);

__device__ uint32_t g_listT[BB * NN * STRIDE];   // entries: (f16 K)<<16 | idx<<2
__device__ uint32_t g_listS[BB * NN * STRIDE];
__device__ int g_cntT[BB * NN];                  // padded counts (multiple of 128)
__device__ int g_cntS[BB * NN];
__device__ float g_eu[BB * NN];                  // 2^u
__device__ float g_ev[BB * NN];                  // 2^v
__device__ __half2 g_Vh[BB * NN * (DD / 2)];     // V in half2 (2MB)
// stage 1: y-slab sorted; stage 2: (yslab,xbin) sorted
__device__ float2 g_sortloc[2][BB][NN];
__device__ unsigned short g_sortid[2][BB][NN];
__device__ int g_slabstart[2][BB][NSLAB + 1];
__device__ float2 g_loc2[2][BB][NN];
__device__ unsigned short g_id2[2][BB][NN];
__device__ int g_binstart[2][BB][NSLAB * NXBIN + 1];
// target cell lists for the epilogue
__device__ int g_tcnt[BB * NCELL2 * NCELL2];
__device__ int g_tlist[BB * NCELL2 * NCELL2][TCAP2];

static __device__ __forceinline__ float ex2f(float x) {
    float y; asm("ex2.approx.ftz.f32 %0, %1;" : "=f"(y) : "f"(x)); return y;
}
static __device__ __forceinline__ float rcpf(float x) {
    float y; asm("rcp.approx.ftz.f32 %0, %1;" : "=f"(y) : "f"(x)); return y;
}
// gather float at byte offset (entry low 16 bits hold idx*4)
static __device__ __forceinline__ float gat(const float* s, uint32_t e) {
    return *reinterpret_cast<const float*>(
        reinterpret_cast<const char*>(s) + (e & 0xFFFCu));
}
static __device__ __forceinline__ float kof(uint32_t e) {   // f16 K -> f32
    return __half2float(__ushort_as_half((unsigned short)(e >> 16)));
}

// ---------------------------------------------------------------------------
// Stage 1: deterministic y-slab counting sort (warp-per-slab, ballot
// compaction). Block (0,0) also zeroes g_tcnt.
// ---------------------------------------------------------------------------
__global__ void slab_sort(const float2* __restrict__ tlocs,
                          const float2* __restrict__ slocs)
{
    const int b = blockIdx.x, mode = blockIdx.y;
    const float2* cl = (mode ? tlocs : slocs) + (size_t)b * NN;
    __shared__ int s_cnt[NSLAB + 1];
    const int tid = threadIdx.x, wid = tid >> 5, lane = tid & 31;  // 16 warps

    if (blockIdx.x == 0 && blockIdx.y == 0)
        for (int k = tid; k < BB * NCELL2 * NCELL2; k += 512) g_tcnt[k] = 0;

    int c = 0;
    for (int i0 = 0; i0 < NN; i0 += 32) {
        const float2 p = cl[i0 + lane];
        const int sl = min(max((int)(p.y * (float)NSLAB), 0), NSLAB - 1);
        c += __popc(__ballot_sync(0xffffffffu, sl == wid));
    }
    if (lane == 0) s_cnt[wid + 1] = c;
    __syncthreads();
    if (tid == 0) {
        s_cnt[0] = 0;
        for (int k = 1; k <= NSLAB; k++) s_cnt[k] += s_cnt[k - 1];
    }
    __syncthreads();
    int base = s_cnt[wid];
    if (tid <= NSLAB) g_slabstart[mode][b][tid] = s_cnt[tid];
    for (int i0 = 0; i0 < NN; i0 += 32) {
        const float2 p = cl[i0 + lane];
        const int sl = min(max((int)(p.y * (float)NSLAB), 0), NSLAB - 1);
        const bool m = (sl == wid);
        const unsigned bal = __ballot_sync(0xffffffffu, m);
        if (m) {
            const int o = base + __popc(bal & ((1u << lane) - 1u));
            g_sortloc[mode][b][o] = p;
            g_sortid[mode][b][o] = (unsigned short)(i0 + lane);
        }
        base += __popc(bal);
    }
}

// ---------------------------------------------------------------------------
// Stage 2: within each y-slab, deterministic x-bin sort.
// ---------------------------------------------------------------------------
__global__ void xbin_sort()
{
    const int b = blockIdx.x, mode = blockIdx.y;
    const int tid = threadIdx.x, wid = tid >> 5, lane = tid & 31;  // 16 warps
    const int beg = g_slabstart[mode][b][wid];
    const int end = g_slabstart[mode][b][wid + 1];

    int base = beg;
    for (int xb = 0; xb < NXBIN; xb++) {
        if (lane == 0) g_binstart[mode][b][wid * NXBIN + xb] = base;
        for (int i0 = beg; i0 < end; i0 += 32) {
            const int i = i0 + lane;
            bool m = false;
            float2 p; unsigned short id = 0;
            if (i < end) {
                p = g_sortloc[mode][b][i];
                id = g_sortid[mode][b][i];
                const int xbin = min(max((int)(p.x * (float)NXBIN), 0), NXBIN - 1);
                m = (xbin == xb);
            }
            const unsigned bal = __ballot_sync(0xffffffffu, m);
            if (m) {
                const int o = base + __popc(bal & ((1u << lane) - 1u));
                g_loc2[mode][b][o] = p;
                g_id2[mode][b][o] = id;
            }
            base += __popc(bal);
        }
    }
    if (wid == NSLAB - 1 && lane == 0)
        g_binstart[mode][b][NSLAB * NXBIN] = end;
}

// ---------------------------------------------------------------------------
// Bin targets into 16x16 cells (atomic order irrelevant: per-target outputs
// are computed independently).
// ---------------------------------------------------------------------------
__global__ void bin_targets(const float2* __restrict__ tlocs)
{
    const int i = blockIdx.x * THREADS + threadIdx.x;
    if (i >= BB * NN) return;
    const int b = i >> 12, t = i & (NN - 1);
    const float2 p = tlocs[i];
    const int cx = min(max((int)(p.x * (float)NCELL2), 0), NCELL2 - 1);
    const int cy = min(max((int)(p.y * (float)NCELL2), 0), NCELL2 - 1);
    const int cell = b * NCELL2 * NCELL2 + cy * NCELL2 + cx;
    const int pos = atomicAdd(&g_tcnt[cell], 1);
    if (pos < TCAP2) g_tlist[cell][pos] = t;
}

// ---------------------------------------------------------------------------
// V (f32) -> half2 copy.
// ---------------------------------------------------------------------------
__global__ void convert_vh(const float2* __restrict__ feats2)
{
    const int i = blockIdx.x * THREADS + threadIdx.x;   // over BB*NN*32
    const float2 v = feats2[i];
    g_Vh[i] = __floats2half2_rn(v.x, v.y);
}

// ---------------------------------------------------------------------------
// Build compacted pair lists; candidates limited to the (yslab,xbin) window
// covering the 0.2 radius. Entries: (f16 K)<<16 | idx<<2 with
// K = 2^(dsq * -C2) = exp(-dsq/eps). Pads to a multiple of 128 with
// SENTINEL (=0). mode 1 also inits ev = 1 (v = 0).
// ---------------------------------------------------------------------------
__global__ void build_lists(const float2* __restrict__ tlocs,
                            const float2* __restrict__ slocs)
{
    __shared__ float2 s_loc[NN];
    __shared__ unsigned short s_id[NN];
    __shared__ int s_bs[NSLAB * NXBIN + 1];       // 257 entries
    const int mode = blockIdx.z;
    const float2* row_locs = (mode ? slocs : tlocs);
    const int b = blockIdx.y;
    const int tid = threadIdx.x;
    #pragma unroll
    for (int k = 0; k < NN / THREADS; k++) {
        s_loc[tid + k * THREADS] = g_loc2[mode][b][tid + k * THREADS];
        s_id[tid + k * THREADS]  = g_id2[mode][b][tid + k * THREADS];
    }
    s_bs[tid] = g_binstart[mode][b][tid];
    if (tid == 0)
        s_bs[NSLAB * NXBIN] = g_binstart[mode][b][NSLAB * NXBIN];
    __syncthreads();

    const int wid = tid >> 5, lane = tid & 31;
    const int r = blockIdx.x * WPB + wid;
    const int g = b * NN + r;
    const float2 rl = row_locs[(size_t)b * NN + r];
    uint32_t* lp = (mode ? g_listS : g_listT) + (size_t)g * STRIDE;

    const int lo  = max((int)((rl.y - 0.2001f) * (float)NSLAB), 0);
    const int hi  = min((int)((rl.y + 0.2001f) * (float)NSLAB), NSLAB - 1);
    const int xlo = max((int)((rl.x - 0.2001f) * (float)NXBIN), 0);
    const int xhi = min((int)((rl.x + 0.2001f) * (float)NXBIN), NXBIN - 1);

    int n = 0;
    for (int s = lo; s <= hi; s++) {
        const int beg = s_bs[s * NXBIN + xlo];
        const int end = s_bs[s * NXBIN + xhi + 1];
        for (int i0 = beg; i0 < end; i0 += 32) {
            const int i = i0 + lane;
            bool pred = false;
            float dsq = 0.0f;
            unsigned short sid = 0;
            if (i < end) {
                const float2 c = s_loc[i];
                const float dx = rl.x - c.x;
                const float dy = rl.y - c.y;
                // match reference rounding: mul, mul, add (no fma contraction)
                dsq = __fadd_rn(__fmul_rn(dx, dx), __fmul_rn(dy, dy));
                pred = dsq < 0.04f;
                sid = s_id[i];
            }
            const unsigned bal = __ballot_sync(0xffffffffu, pred);
            if (pred) {
                const float K = ex2f(dsq * (-C2));   // exp(-dsq/eps), in (0.018, 1]
                const unsigned short h = __half_as_ushort(__float2half(K));
                const uint32_t e = ((uint32_t)sid << 2) | ((uint32_t)h << 16);
                const int ofs = n + __popc(bal & ((1u << lane) - 1u));
                if (ofs < STRIDE) lp[ofs] = e;
            }
            n += __popc(bal);
        }
    }
    n = min(n, STRIDE);
    const int npad = min((n + 127) & ~127, STRIDE);
    for (int i = n + lane; i < npad; i += 32) lp[i] = SENTINEL;
    if (lane == 0) {
        (mode ? g_cntS : g_cntT)[g] = npad;
        if (mode) g_ev[g] = 1.0f;                  // 2^0
    }
}

// ---------------------------------------------------------------------------
// One Sinkhorn half-iteration, linear domain:
//   dir 0: eu[t] = 1 / sum_s K * ev[s]
//   dir 1: ev[s] = 1 / sum_t K * eu[t]
// 8 rows/block; <=5 list chunks loaded up-front (MLP 5). Pure LDS+FMA inner.
// ---------------------------------------------------------------------------
static __device__ __forceinline__ float chunk_sum(uint4 q, const float* s_in) {
    float a;
    a  = kof(q.x) * gat(s_in, q.x);
    a  = fmaf(kof(q.y), gat(s_in, q.y), a);
    a  = fmaf(kof(q.z), gat(s_in, q.z), a);
    a  = fmaf(kof(q.w), gat(s_in, q.w), a);
    return a;
}

__global__ void sinkhorn_pass(int dir)
{
    __shared__ float s_in[NN];
    const int b = blockIdx.y;
    const int tid = threadIdx.x;
    const float* vin = dir ? g_eu : g_ev;
    #pragma unroll
    for (int k = 0; k < NN / THREADS; k++)
        s_in[tid + k * THREADS] = vin[b * NN + tid + k * THREADS];
    __syncthreads();

    const int wid = tid >> 5, lane = tid & 31;
    const int g = b * NN + blockIdx.x * WPB + wid;
    const int n = (dir ? g_cntS : g_cntT)[g];      // multiple of 128, <= 640
    const uint4* lp = reinterpret_cast<const uint4*>(
        (dir ? g_listS : g_listT) + (size_t)g * STRIDE);
    const int nc = n >> 7;                         // chunk count, 0..5

    uint4 q0, q1, q2, q3, q4;
    if (nc > 0) q0 = lp[lane];
    if (nc > 1) q1 = lp[32 + lane];
    if (nc > 2) q2 = lp[64 + lane];
    if (nc > 3) q3 = lp[96 + lane];
    if (nc > 4) q4 = lp[128 + lane];

    float acc = 0.0f;
    if (nc > 0) acc += chunk_sum(q0, s_in);
    if (nc > 1) acc += chunk_sum(q1, s_in);
    if (nc > 2) acc += chunk_sum(q2, s_in);
    if (nc > 3) acc += chunk_sum(q3, s_in);
    if (nc > 4) acc += chunk_sum(q4, s_in);

    #pragma unroll
    for (int o = 16; o; o >>= 1) acc += __shfl_xor_sync(0xffffffffu, acc, o);
    if (lane == 0) (dir ? g_ev : g_eu)[g] = rcpf(acc);
}

// ---------------------------------------------------------------------------
// Epilogue: one CTA per (cell, batch); one warp per target of the cell.
// w = K * ev[s] * eu[t] (no transcendentals). Per 32-entry chunk: lanes
// compute weights into smem, then all lanes walk the 32 (w, off) pairs
// (LDS.64 broadcast) accumulating half2 V rows.
// ---------------------------------------------------------------------------
__global__ void __launch_bounds__(512)
final_kernel(float* __restrict__ out)
{
    __shared__ float s_v[NN];                  // ev for this batch
    __shared__ float2 s_w[16][32];             // (w, off-as-float) per warp
    const int b = blockIdx.y;
    const int cell = blockIdx.x;               // 0..255
    const int tid = threadIdx.x, wid = tid >> 5, lane = tid & 31;  // 16 warps

    #pragma unroll
    for (int k = 0; k < NN / 512; k++)
        s_v[tid + k * 512] = g_ev[b * NN + tid + k * 512];
    __syncthreads();

    const int gcell = b * NCELL2 * NCELL2 + cell;
    const int tcnt = min(g_tcnt[gcell], TCAP2);
    const __half2* Vb = g_Vh + (size_t)b * NN * (DD / 2);

    for (int ti = wid; ti < tcnt; ti += 16) {
        const int t = g_tlist[gcell][ti];
        const int g = b * NN + t;
        const int n = g_cntT[g];               // multiple of 128 (or 0)
        const uint32_t* lp = g_listT + (size_t)g * STRIDE;
        const float eut = g_eu[g];

        float2 acc = make_float2(0.0f, 0.0f);
        uint32_t e = (n > 0) ? lp[lane] : SENTINEL;
        for (int i0 = 0; i0 < n; i0 += 32) {
            const float w = kof(e) * gat(s_v, e) * eut;
            s_w[wid][lane] = make_float2(w, __uint_as_float(e & 0xFFFCu));
            __syncwarp();
            if (i0 + 32 < n) e = lp[i0 + 32 + lane];   // prefetch next chunk
            #pragma unroll 8
            for (int j = 0; j < 32; j++) {
                const float2 p = s_w[wid][j];
                if (p.x != 0.0f) {   // warp-uniform; skips padding/underflow
                    const float2 vv = __half22float2(
                        Vb[((size_t)__float_as_uint(p.y) << 3) + lane]);
                    acc.x = fmaf(p.x, vv.x, acc.x);
                    acc.y = fmaf(p.x, vv.y, acc.y);
                }
            }
            __syncwarp();
        }
        reinterpret_cast<float2*>(out)[(size_t)g * (DD / 2) + lane] = acc;
    }
}

// ---------------------------------------------------------------------------
extern "C" void kernel_launch(void* const* d_in, const int* in_sizes, int n_in,
                              void* d_out, int out_size)
{
    const float* feats  = (const float*)d_in[0];        // (b, src, 64) f32
    const float2* slocs = (const float2*)d_in[1];       // (b, src, 2)  f32
    const float2* tlocs = (const float2*)d_in[2];       // (b, tgt, 2)  f32
    float* out = (float*)d_out;                          // (b, tgt, 64) f32

    slab_sort<<<dim3(BB, 2), 512>>>(tlocs, slocs);
    xbin_sort<<<dim3(BB, 2), 512>>>();
    bin_targets<<<(BB * NN + THREADS - 1) / THREADS, THREADS>>>(tlocs);
    convert_vh<<<BB * NN * (DD / 2) / THREADS, THREADS>>>((const float2*)feats);
    build_lists<<<dim3(NN / WPB, BB, 2), THREADS>>>(tlocs, slocs);

    for (int it = 0; it < 8; it++) {
        sinkhorn_pass<<<dim3(NN / WPB, BB), THREADS>>>(0);  // eu <- ev
        sinkhorn_pass<<<dim3(NN / WPB, BB), THREADS>>>(1);  // ev <- eu
    }

    final_kernel<<<dim3(NCELL2 * NCELL2, BB), 512>>>(out);
}